// round 3
// baseline (speedup 1.0000x reference)
#include <cuda_runtime.h>
#include <math.h>

#define SL 50
#define TL 50
#define BA 16
#define HID 1024
#define HD2 512
#define NL 4
#define VOUT 32000

__device__ __align__(16) float g_encx [SL*BA*HID];
__device__ __align__(16) float g_ency [SL*BA*HID];
__device__ __align__(16) float g_encxg[SL*BA*4096];
__device__ __align__(16) float g_enchA[2*BA*HD2];
__device__ __align__(16) float g_enchB[2*BA*HD2];
__device__ __align__(16) float g_encc [2*BA*HD2];
__device__ __align__(16) float g_h0   [NL*BA*HID];
__device__ __align__(16) float g_c0   [NL*BA*HID];
__device__ __align__(16) float g_demb [TL*BA*HID];
__device__ __align__(16) float g_pre0 [TL*BA*4096];
__device__ __align__(16) float g_dhA  [NL*BA*HID];
__device__ __align__(16) float g_dhB  [NL*BA*HID];
__device__ __align__(16) float g_dc   [NL*BA*HID];
__device__ __align__(16) float g_htl  [BA*HID];
__device__ __align__(16) float g_ctx  [BA*HID];
__device__ __align__(16) float g_hA   [SL*BA*HID];
__device__ __align__(16) float g_hbt  [BA*TL*HID];

__device__ __forceinline__ float sigf(float x){ return 1.f/(1.f+expf(-x)); }

__global__ void embed_k(const int* __restrict__ idx, const float* __restrict__ W,
                        float* __restrict__ out, int slen){
    int s = blockIdx.x, b = blockIdx.y;
    long tok = idx[b*slen + s];
    const float4* sp = (const float4*)(W + tok*1024);
    float4* dp = (float4*)(out + ((long)s*BA + b)*1024);
    for (int i = threadIdx.x; i < 256; i += blockDim.x) dp[i] = sp[i];
}

__global__ void zero_k(float* p, int n){
    int i = blockIdx.x*blockDim.x + threadIdx.x;
    if (i < n) p[i] = 0.f;
}
__global__ void copy_k(float* d, const float* s, int n){
    int i = blockIdx.x*blockDim.x + threadIdx.x;
    if (i < n) d[i] = s[i];
}

// C[m][n] = sum_k A[m][k] * op(B) + bias1[n] + bias2[n]
__global__ __launch_bounds__(256) void gemm_k(
    const float* __restrict__ A, int lda,
    const float* __restrict__ B, int ldb, int transB,
    const float* __restrict__ b1, const float* __restrict__ b2,
    float* __restrict__ C, int ldc, int M, int N, int K)
{
    __shared__ float As[16][132];
    __shared__ float Bs[16][132];
    int m0 = blockIdx.y*128, n0 = blockIdx.x*128;
    int tid = threadIdx.x, tx = tid & 15, ty = tid >> 4;
    float acc[8][8];
#pragma unroll
    for (int i = 0; i < 8; i++)
#pragma unroll
        for (int j = 0; j < 8; j++) acc[i][j] = 0.f;

    for (int k0 = 0; k0 < K; k0 += 16) {
#pragma unroll
        for (int i = 0; i < 2; i++) {
            int e = tid + i*256, m = e >> 2, kq = e & 3;
            float4 v = make_float4(0,0,0,0);
            if (m0 + m < M) v = *(const float4*)(A + (long)(m0+m)*lda + k0 + kq*4);
            As[kq*4+0][m]=v.x; As[kq*4+1][m]=v.y; As[kq*4+2][m]=v.z; As[kq*4+3][m]=v.w;
        }
        if (transB) {
#pragma unroll
            for (int i = 0; i < 2; i++) {
                int e = tid + i*256, n = e >> 2, kq = e & 3;
                float4 v = *(const float4*)(B + (long)(n0+n)*ldb + k0 + kq*4);
                Bs[kq*4+0][n]=v.x; Bs[kq*4+1][n]=v.y; Bs[kq*4+2][n]=v.z; Bs[kq*4+3][n]=v.w;
            }
        } else {
#pragma unroll
            for (int i = 0; i < 2; i++) {
                int e = tid + i*256, kk = e >> 5, nq = e & 31;
                *(float4*)&Bs[kk][nq*4] = *(const float4*)(B + (long)(k0+kk)*ldb + n0 + nq*4);
            }
        }
        __syncthreads();
#pragma unroll
        for (int kk = 0; kk < 16; kk++) {
            float a[8], bv[8];
            *(float4*)&a[0] = *(float4*)&As[kk][ty*8];
            *(float4*)&a[4] = *(float4*)&As[kk][ty*8+4];
            *(float4*)&bv[0] = *(float4*)&Bs[kk][tx*8];
            *(float4*)&bv[4] = *(float4*)&Bs[kk][tx*8+4];
#pragma unroll
            for (int i = 0; i < 8; i++)
#pragma unroll
                for (int j = 0; j < 8; j++) acc[i][j] = fmaf(a[i], bv[j], acc[i][j]);
        }
        __syncthreads();
    }
#pragma unroll
    for (int i = 0; i < 8; i++) {
        int m = m0 + ty*8 + i;
        if (m < M) {
            float* Cr = C + (long)m*ldc + n0 + tx*8;
#pragma unroll
            for (int j = 0; j < 8; j++) {
                int n = n0 + tx*8 + j;
                float v = acc[i][j];
                if (b1) v += b1[n];
                if (b2) v += b2[n];
                Cr[j] = v;
            }
        }
    }
}

// encoder recurrent step, both directions. grid 128, 256 thr.
__global__ __launch_bounds__(256) void enc_step_k(
    const float* __restrict__ Whh, const float* __restrict__ xg,
    const float* __restrict__ hin, float* __restrict__ hout,
    float* __restrict__ c, float* __restrict__ y,
    float* __restrict__ h0l, float* __restrict__ c0l, int step)
{
    __shared__ __align__(16) float Wt[32][129];
    __shared__ __align__(16) float xs[128][18];
    __shared__ float sg[4][8][16];
    int tid = threadIdx.x;
    int dir = blockIdx.x >> 6, j0 = (blockIdx.x & 63)*8;
    int s = dir ? (SL-1-step) : step;
    int rl = tid & 31, u = tid >> 5;
    float a0 = 0.f, a1 = 0.f;
    const float* hs = hin + dir*(BA*HD2);

    if (step > 0) {
        for (int kt = 0; kt < HD2; kt += 128) {
            __syncthreads();
#pragma unroll
            for (int i = 0; i < 8; i++) {
                int e = tid + i*256, kk = e & 127, b = e >> 7;
                xs[kk][b] = hs[b*HD2 + kt + kk];
            }
#pragma unroll
            for (int i = 0; i < 16; i++) {
                int e = tid + i*256, kk = e & 127, r = e >> 7;
                long gr = dir*2048 + (r>>3)*HD2 + j0 + (r&7);
                Wt[r][kk] = Whh[gr*HD2 + kt + kk];
            }
            __syncthreads();
#pragma unroll 16
            for (int k = 0; k < 128; k++) {
                float w = Wt[rl][k];
                float2 hv = *(const float2*)&xs[k][2*u];
                a0 = fmaf(w, hv.x, a0);
                a1 = fmaf(w, hv.y, a1);
            }
        }
    }
    int gate = rl >> 3, jj = rl & 7;
    long base = (long)s*BA*4096 + dir*2048 + gate*HD2 + j0 + jj;
    a0 += xg[base + (long)(2*u)*4096];
    a1 += xg[base + (long)(2*u+1)*4096];
    sg[gate][jj][2*u] = a0;
    sg[gate][jj][2*u+1] = a1;
    __syncthreads();
    if (tid < 128) {
        int b = tid & 15, j = tid >> 4;
        float iv = sg[0][j][b], fv = sg[1][j][b], gv = sg[2][j][b], ov = sg[3][j][b];
        int ci = dir*(BA*HD2) + b*HD2 + j0 + j;
        float cc = (step == 0) ? 0.f : c[ci];
        float cn = sigf(fv)*cc + sigf(iv)*tanhf(gv);
        float hn = sigf(ov)*tanhf(cn);
        c[ci] = cn;
        hout[ci] = hn;
        y[((long)s*BA + b)*HID + dir*HD2 + j0 + j] = hn;
        if (step == SL-1) {
            h0l[b*HID + dir*HD2 + j0 + j] = hn;
            c0l[b*HID + dir*HD2 + j0 + j] = cn;
        }
    }
}

// decoder LSTM layer: gates = W1@x1 + W2@x2 (+ pre | b1+b2), then cell. grid 128.
__global__ __launch_bounds__(256) void dec_step_k(
    const float* __restrict__ W1, int ld1, const float* __restrict__ x1,
    const float* __restrict__ W2, const float* __restrict__ x2,
    const float* __restrict__ pre, const float* __restrict__ b1,
    const float* __restrict__ b2, float* __restrict__ hout, float* __restrict__ c)
{
    __shared__ __align__(16) float Wt[32][129];
    __shared__ __align__(16) float xs[128][18];
    __shared__ float sg[4][8][16];
    int tid = threadIdx.x, j0 = blockIdx.x*8;
    int rl = tid & 31, u = tid >> 5;
    float a0 = 0.f, a1 = 0.f;

    for (int p = 0; p < 2; p++) {
        const float* W = p ? W2 : W1;
        int ld = p ? HID : ld1;
        const float* xp = p ? x2 : x1;
        for (int kt = 0; kt < HID; kt += 128) {
            __syncthreads();
#pragma unroll
            for (int i = 0; i < 8; i++) {
                int e = tid + i*256, kk = e & 127, b = e >> 7;
                xs[kk][b] = xp[b*HID + kt + kk];
            }
#pragma unroll
            for (int i = 0; i < 16; i++) {
                int e = tid + i*256, kk = e & 127, r = e >> 7;
                long gr = (long)((r>>3)*HID + j0 + (r&7));
                Wt[r][kk] = W[gr*ld + kt + kk];
            }
            __syncthreads();
#pragma unroll 16
            for (int k = 0; k < 128; k++) {
                float w = Wt[rl][k];
                float2 hv = *(const float2*)&xs[k][2*u];
                a0 = fmaf(w, hv.x, a0);
                a1 = fmaf(w, hv.y, a1);
            }
        }
    }
    int gate = rl >> 3, jj = rl & 7;
    int row = gate*HID + j0 + jj;
    if (pre) {
        a0 += pre[(2*u)*4096 + row];
        a1 += pre[(2*u+1)*4096 + row];
    } else {
        float bb = b1[row] + b2[row];
        a0 += bb; a1 += bb;
    }
    sg[gate][jj][2*u] = a0;
    sg[gate][jj][2*u+1] = a1;
    __syncthreads();
    if (tid < 128) {
        int b = tid & 15, j = tid >> 4;
        float iv = sg[0][j][b], fv = sg[1][j][b], gv = sg[2][j][b], ov = sg[3][j][b];
        int ci = b*HID + j0 + j;
        float cc = c[ci];
        float cn = sigf(fv)*cc + sigf(iv)*tanhf(gv);
        c[ci] = cn;
        hout[ci] = sigf(ov)*tanhf(cn);
    }
}

// attention for step t: scores over S, softmax, ctx. grid 16 (per batch).
__global__ __launch_bounds__(256) void attn_k(
    const float* __restrict__ h3, const float* __restrict__ hA,
    const float* __restrict__ hsrc, float* __restrict__ ctx)
{
    __shared__ float h3s[HID];
    __shared__ float sc[SL];
    int b = blockIdx.x, tid = threadIdx.x;
    for (int i = tid; i < HID; i += 256) h3s[i] = h3[b*HID + i];
    __syncthreads();
    int w = tid >> 5, lane = tid & 31;
    for (int s = w; s < SL; s += 8) {
        const float* hp = hA + ((long)s*BA + b)*HID;
        float p = 0.f;
        for (int k = lane; k < HID; k += 32) p = fmaf(h3s[k], hp[k], p);
#pragma unroll
        for (int o = 16; o > 0; o >>= 1) p += __shfl_xor_sync(0xffffffffu, p, o);
        if (lane == 0) sc[s] = p;
    }
    __syncthreads();
    if (tid == 0) {
        float mx = sc[0];
        for (int s = 1; s < SL; s++) mx = fmaxf(mx, sc[s]);
        float sum = 0.f;
        for (int s = 0; s < SL; s++) { sc[s] = expf(sc[s]-mx); sum += sc[s]; }
        float inv = 1.f/sum;
        for (int s = 0; s < SL; s++) sc[s] *= inv;
    }
    __syncthreads();
    float4 acc = make_float4(0,0,0,0);
    int k = tid*4;
    for (int s = 0; s < SL; s++) {
        float ws = sc[s];
        float4 v = *(const float4*)(hsrc + ((long)s*BA + b)*HID + k);
        acc.x = fmaf(ws, v.x, acc.x); acc.y = fmaf(ws, v.y, acc.y);
        acc.z = fmaf(ws, v.z, acc.z); acc.w = fmaf(ws, v.w, acc.w);
    }
    *(float4*)(ctx + b*HID + k) = acc;
}

// h_tilde = tanh([h3, ctx] @ Wc^T + bc); write g_htl and g_hbt[b][t]. grid 32.
__global__ __launch_bounds__(256) void htilde_k(
    const float* __restrict__ Wc, const float* __restrict__ bc,
    const float* __restrict__ h3, const float* __restrict__ ctx,
    float* __restrict__ htl, float* __restrict__ hbt, int t)
{
    __shared__ __align__(16) float Wt[32][129];
    __shared__ __align__(16) float xs[128][18];
    int tid = threadIdx.x, j0 = blockIdx.x*32;
    int rl = tid & 31, u = tid >> 5;
    float a0 = 0.f, a1 = 0.f;
    for (int p = 0; p < 2; p++) {
        const float* xp = p ? ctx : h3;
        for (int kt = 0; kt < HID; kt += 128) {
            __syncthreads();
#pragma unroll
            for (int i = 0; i < 8; i++) {
                int e = tid + i*256, kk = e & 127, b = e >> 7;
                xs[kk][b] = xp[b*HID + kt + kk];
            }
#pragma unroll
            for (int i = 0; i < 16; i++) {
                int e = tid + i*256, kk = e & 127, r = e >> 7;
                Wt[r][kk] = Wc[(long)(j0+r)*2048 + p*HID + kt + kk];
            }
            __syncthreads();
#pragma unroll 16
            for (int k = 0; k < 128; k++) {
                float w = Wt[rl][k];
                float2 hv = *(const float2*)&xs[k][2*u];
                a0 = fmaf(w, hv.x, a0);
                a1 = fmaf(w, hv.y, a1);
            }
        }
    }
    int row = j0 + rl;
    float bb = bc[row];
    float v0 = tanhf(a0 + bb), v1 = tanhf(a1 + bb);
    int b0 = 2*u, b1i = 2*u+1;
    htl[b0*HID + row] = v0;
    htl[b1i*HID + row] = v1;
    hbt[((long)b0*TL + t)*HID + row] = v0;
    hbt[((long)b1i*TL + t)*HID + row] = v1;
}

// in-place log-softmax per row of [M][VOUT]
__global__ __launch_bounds__(256) void lsm_k(float* __restrict__ out)
{
    __shared__ float red[256];
    long m = blockIdx.x;
    float* row = out + m*VOUT;
    int tid = threadIdx.x;
    float mx = -1e30f;
    for (int i = tid; i < VOUT/4; i += 256) {
        float4 v = *(const float4*)(row + i*4);
        mx = fmaxf(mx, fmaxf(fmaxf(v.x, v.y), fmaxf(v.z, v.w)));
    }
    red[tid] = mx; __syncthreads();
    for (int o = 128; o > 0; o >>= 1) { if (tid < o) red[tid] = fmaxf(red[tid], red[tid+o]); __syncthreads(); }
    mx = red[0]; __syncthreads();
    float sum = 0.f;
    for (int i = tid; i < VOUT/4; i += 256) {
        float4 v = *(const float4*)(row + i*4);
        sum += expf(v.x-mx)+expf(v.y-mx)+expf(v.z-mx)+expf(v.w-mx);
    }
    red[tid] = sum; __syncthreads();
    for (int o = 128; o > 0; o >>= 1) { if (tid < o) red[tid] += red[tid+o]; __syncthreads(); }
    float lse = mx + logf(red[0]);
    for (int i = tid; i < VOUT/4; i += 256) {
        float4 v = *(const float4*)(row + i*4);
        v.x -= lse; v.y -= lse; v.z -= lse; v.w -= lse;
        *(float4*)(row + i*4) = v;
    }
}

static float* sym(const void* s){ void* p = nullptr; cudaGetSymbolAddress(&p, s); return (float*)p; }

extern "C" void kernel_launch(void* const* d_in, const int* in_sizes, int n_in,
                              void* d_out, int out_size)
{
    const int*   src     = (const int*)  d_in[0];
    const int*   tgt     = (const int*)  d_in[1];
    const float* embS    = (const float*)d_in[2];
    const float* embD    = (const float*)d_in[3];
    const float* eWih    = (const float*)d_in[4];
    const float* eWhh    = (const float*)d_in[5];
    const float* ebih    = (const float*)d_in[6];
    const float* ebhh    = (const float*)d_in[7];
    const float* d0Wih   = (const float*)d_in[8];
    const float* d0Whh   = (const float*)d_in[9];
    const float* d0bih   = (const float*)d_in[10];
    const float* d0bhh   = (const float*)d_in[11];
    const float* dWih    = (const float*)d_in[12];
    const float* dWhh    = (const float*)d_in[13];
    const float* dbih    = (const float*)d_in[14];
    const float* dbhh    = (const float*)d_in[15];
    const float* Wattn   = (const float*)d_in[16];
    const float* Wcat    = (const float*)d_in[17];
    const float* bcat    = (const float*)d_in[18];
    const float* Wout    = (const float*)d_in[19];
    const float* bout    = (const float*)d_in[20];
    float* out = (float*)d_out;

    float* encx = sym(g_encx);  float* ency = sym(g_ency);
    float* encxg = sym(g_encxg);
    float* ehA = sym(g_enchA);  float* ehB = sym(g_enchB);
    float* ecc = sym(g_encc);
    float* h0 = sym(g_h0);      float* c0 = sym(g_c0);
    float* demb = sym(g_demb);  float* pre0 = sym(g_pre0);
    float* dhA = sym(g_dhA);    float* dhB = sym(g_dhB);
    float* dc  = sym(g_dc);
    float* htl = sym(g_htl);    float* ctx = sym(g_ctx);
    float* hAp = sym(g_hA);     float* hbt = sym(g_hbt);

    // ---- encoder ----
    embed_k<<<dim3(SL, BA), 256>>>(src, embS, encx, SL);
    float* xin = encx; float* yout = ency;
    for (int l = 0; l < NL; l++) {
        gemm_k<<<dim3(32, 7), 256>>>(xin, HID, eWih + (long)l*2*2048*1024, 1024, 1,
                                     ebih + l*4096, ebhh + l*4096, encxg, 4096,
                                     SL*BA, 4096, 1024);
        float* hi = ehA; float* ho = ehB;
        for (int st = 0; st < SL; st++) {
            enc_step_k<<<128, 256>>>(eWhh + (long)l*2*2048*512, encxg, hi, ho, ecc,
                                     yout, h0 + (long)l*BA*HID, c0 + (long)l*BA*HID, st);
            float* tmp = hi; hi = ho; ho = tmp;
        }
        float* t = xin; xin = yout; yout = t;
    }
    float* hsrc = xin;  // final encoder output [S][B][H]

    // ---- decoder precompute ----
    embed_k<<<dim3(TL, BA), 256>>>(tgt, embD, demb, TL);
    gemm_k<<<dim3(32, 7), 256>>>(demb, HID, d0Wih, 2048, 1, d0bih, d0bhh,
                                 pre0, 4096, TL*BA, 4096, 1024);
    gemm_k<<<dim3(8, 7), 256>>>(hsrc, HID, Wattn, 1024, 0, nullptr, nullptr,
                                hAp, HID, SL*BA, 1024, 1024);
    copy_k<<<(NL*BA*HID+255)/256, 256>>>(dhA, h0, NL*BA*HID);
    copy_k<<<(NL*BA*HID+255)/256, 256>>>(dc, c0, NL*BA*HID);
    zero_k<<<(BA*HID+255)/256, 256>>>(htl, BA*HID);

    // ---- decoder loop ----
    float* hi = dhA; float* ho = dhB;
    for (int t = 0; t < TL; t++) {
        dec_step_k<<<128, 256>>>(d0Wih + 1024, 2048, htl, d0Whh, hi,
                                 pre0 + (long)t*BA*4096, nullptr, nullptr, ho, dc);
        for (int i = 0; i < NL-1; i++) {
            dec_step_k<<<128, 256>>>(dWih + (long)i*4096*1024, 1024, ho + (long)i*BA*HID,
                                     dWhh + (long)i*4096*1024, hi + (long)(i+1)*BA*HID,
                                     nullptr, dbih + i*4096, dbhh + i*4096,
                                     ho + (long)(i+1)*BA*HID, dc + (long)(i+1)*BA*HID);
        }
        attn_k<<<BA, 256>>>(ho + (long)3*BA*HID, hAp, hsrc, ctx);
        htilde_k<<<32, 256>>>(Wcat, bcat, ho + (long)3*BA*HID, ctx, htl, hbt, t);
        float* tmp = hi; hi = ho; ho = tmp;
    }

    // ---- generator ----
    gemm_k<<<dim3(250, 7), 256>>>(hbt, HID, Wout, 1024, 1, bout, nullptr,
                                  out, VOUT, BA*TL, VOUT, 1024);
    lsm_k<<<BA*TL, 256>>>(out);
}

// round 4
// speedup vs baseline: 1.7554x; 1.7554x over previous
#include <cuda_runtime.h>
#include <math.h>

#define SL 50
#define TL 50
#define BA 16
#define HID 1024
#define HD2 512
#define NL 4
#define VOUT 32000

__device__ __align__(16) float g_encx [SL*BA*HID];
__device__ __align__(16) float g_ency [SL*BA*HID];
__device__ __align__(16) float g_encxg[SL*BA*4096];
__device__ __align__(16) float g_enchA[2*BA*HD2];
__device__ __align__(16) float g_enchB[2*BA*HD2];
__device__ __align__(16) float g_encc [2*BA*HD2];
__device__ __align__(16) float g_h0   [NL*BA*HID];
__device__ __align__(16) float g_c0   [NL*BA*HID];
__device__ __align__(16) float g_demb [TL*BA*HID];
__device__ __align__(16) float g_pre0 [TL*BA*4096];
__device__ __align__(16) float g_dhA  [NL*BA*HID];
__device__ __align__(16) float g_dhB  [NL*BA*HID];
__device__ __align__(16) float g_dc   [NL*BA*HID];
__device__ __align__(16) float g_htl  [BA*HID];
__device__ __align__(16) float g_ctx  [BA*HID];
__device__ __align__(16) float g_hA   [SL*BA*HID];
__device__ __align__(16) float g_hbt  [BA*TL*HID];
__device__ __align__(16) float g_part [8*4096*16];

__device__ __forceinline__ float sigf(float x){ return 1.f/(1.f+expf(-x)); }

__global__ void embed_k(const int* __restrict__ idx, const float* __restrict__ W,
                        float* __restrict__ out, int slen){
    int s = blockIdx.x, b = blockIdx.y;
    long tok = idx[b*slen + s];
    const float4* sp = (const float4*)(W + tok*1024);
    float4* dp = (float4*)(out + ((long)s*BA + b)*1024);
    for (int i = threadIdx.x; i < 256; i += blockDim.x) dp[i] = sp[i];
}

__global__ void zero_k(float* p, int n){
    int i = blockIdx.x*blockDim.x + threadIdx.x;
    if (i < n) p[i] = 0.f;
}
__global__ void copy_k(float* d, const float* s, int n){
    int i = blockIdx.x*blockDim.x + threadIdx.x;
    if (i < n) d[i] = s[i];
}

// ---------------- big tiled GEMM (enc input proj, pre0, hA, generator) ------
__global__ __launch_bounds__(256) void gemm_k(
    const float* __restrict__ A, int lda,
    const float* __restrict__ B, int ldb, int transB,
    const float* __restrict__ b1, const float* __restrict__ b2,
    float* __restrict__ C, int ldc, int M, int N, int K)
{
    __shared__ float As[16][132];
    __shared__ float Bs[16][132];
    int m0 = blockIdx.y*128, n0 = blockIdx.x*128;
    int tid = threadIdx.x, tx = tid & 15, ty = tid >> 4;
    float acc[8][8];
#pragma unroll
    for (int i = 0; i < 8; i++)
#pragma unroll
        for (int j = 0; j < 8; j++) acc[i][j] = 0.f;

    for (int k0 = 0; k0 < K; k0 += 16) {
#pragma unroll
        for (int i = 0; i < 2; i++) {
            int e = tid + i*256, m = e >> 2, kq = e & 3;
            float4 v = make_float4(0,0,0,0);
            if (m0 + m < M) v = *(const float4*)(A + (long)(m0+m)*lda + k0 + kq*4);
            As[kq*4+0][m]=v.x; As[kq*4+1][m]=v.y; As[kq*4+2][m]=v.z; As[kq*4+3][m]=v.w;
        }
        if (transB) {
#pragma unroll
            for (int i = 0; i < 2; i++) {
                int e = tid + i*256, n = e >> 2, kq = e & 3;
                float4 v = *(const float4*)(B + (long)(n0+n)*ldb + k0 + kq*4);
                Bs[kq*4+0][n]=v.x; Bs[kq*4+1][n]=v.y; Bs[kq*4+2][n]=v.z; Bs[kq*4+3][n]=v.w;
            }
        } else {
#pragma unroll
            for (int i = 0; i < 2; i++) {
                int e = tid + i*256, kk = e >> 5, nq = e & 31;
                *(float4*)&Bs[kk][nq*4] = *(const float4*)(B + (long)(k0+kk)*ldb + n0 + nq*4);
            }
        }
        __syncthreads();
#pragma unroll
        for (int kk = 0; kk < 16; kk++) {
            float a[8], bv[8];
            *(float4*)&a[0] = *(float4*)&As[kk][ty*8];
            *(float4*)&a[4] = *(float4*)&As[kk][ty*8+4];
            *(float4*)&bv[0] = *(float4*)&Bs[kk][tx*8];
            *(float4*)&bv[4] = *(float4*)&Bs[kk][tx*8+4];
#pragma unroll
            for (int i = 0; i < 8; i++)
#pragma unroll
                for (int j = 0; j < 8; j++) acc[i][j] = fmaf(a[i], bv[j], acc[i][j]);
        }
        __syncthreads();
    }
#pragma unroll
    for (int i = 0; i < 8; i++) {
        int m = m0 + ty*8 + i;
        if (m < M) {
            float* Cr = C + (long)m*ldc + n0 + tx*8;
#pragma unroll
            for (int j = 0; j < 8; j++) {
                int n = n0 + tx*8 + j;
                float v = acc[i][j];
                if (b1) v += b1[n];
                if (b2) v += b2[n];
                Cr[j] = v;
            }
        }
    }
}

// ---------------- k-split partial matvec-batch --------------------------
// grid = (rtot/128)*8 blocks. Block: slice = bid&7 (K chunk of KS), rowgroup
// = bid>>3 (128 rows). Output: part[slice][row][16 batches].
// mode 0: W/x selected by k (W1 covers k<k1, W2 the rest).
// mode 1: W = W1 for all k; x selected by row (r0>=2048 -> x2). (encoder dirs)
__global__ __launch_bounds__(256) void mm_k(
    const float* __restrict__ W1, int ld1, int k1,
    const float* __restrict__ x1, int ldx1,
    const float* __restrict__ W2, int ld2,
    const float* __restrict__ x2, int ldx2,
    int mode, int KS, float* __restrict__ part, int rtot)
{
    __shared__ __align__(16) float Wt[32][130];
    __shared__ __align__(16) float xs[32][20];
    int tid = threadIdx.x;
    int slice = blockIdx.x & 7, rg = blockIdx.x >> 3;
    int r0 = rg*128, k0 = slice*KS;
    const float* W; const float* x; int ld, ldx, ko;
    if (mode == 1) {
        W = W1; ld = ld1; ko = k0;
        if (r0 >= 2048) { x = x2; ldx = ldx2; } else { x = x1; ldx = ldx1; }
    } else {
        if (k0 < k1) { W = W1; ld = ld1; x = x1; ldx = ldx1; ko = k0; }
        else { W = W2; ld = ld2; x = x2; ldx = ldx2; ko = k0 - k1; }
    }
    int rp = tid >> 2, rq = tid & 3;
    float a00=0,a01=0,a02=0,a03=0,a10=0,a11=0,a12=0,a13=0;

    for (int kt = 0; kt < KS; kt += 32) {
        __syncthreads();
#pragma unroll
        for (int i = 0; i < 4; i++) {
            int e = tid + i*256; int row = e >> 3, kq = e & 7;
            float4 v = *(const float4*)(W + (long)(r0+row)*ld + ko + kt + kq*4);
            Wt[kq*4+0][row]=v.x; Wt[kq*4+1][row]=v.y;
            Wt[kq*4+2][row]=v.z; Wt[kq*4+3][row]=v.w;
        }
#pragma unroll
        for (int i = 0; i < 2; i++) {
            int e = tid + i*256; int b = e >> 5, kk = e & 31;
            xs[kk][b] = x[b*ldx + ko + kt + kk];
        }
        __syncthreads();
#pragma unroll
        for (int kk = 0; kk < 32; kk++) {
            float2 w  = *(const float2*)&Wt[kk][2*rp];
            float4 xv = *(const float4*)&xs[kk][4*rq];
            a00 = fmaf(w.x, xv.x, a00); a01 = fmaf(w.x, xv.y, a01);
            a02 = fmaf(w.x, xv.z, a02); a03 = fmaf(w.x, xv.w, a03);
            a10 = fmaf(w.y, xv.x, a10); a11 = fmaf(w.y, xv.y, a11);
            a12 = fmaf(w.y, xv.z, a12); a13 = fmaf(w.y, xv.w, a13);
        }
    }
    float* p = part + ((long)slice*rtot + r0 + 2*rp)*16 + 4*rq;
    *(float4*)p        = make_float4(a00,a01,a02,a03);
    *(float4*)(p + 16) = make_float4(a10,a11,a12,a13);
}

// ---------------- encoder cell: reduce partials + LSTM nonlinearity ---------
__global__ __launch_bounds__(256) void enc_cell_k(
    const float* __restrict__ part, const float* __restrict__ xg,
    float* __restrict__ c, float* __restrict__ hout, float* __restrict__ y,
    float* __restrict__ h0l, float* __restrict__ c0l, int step)
{
    int idx = blockIdx.x*256 + threadIdx.x;
    int b = idx & 15, hd = (idx >> 4) & 511, dir = idx >> 13;
    int s = dir ? (SL-1-step) : step;
    float g[4];
#pragma unroll
    for (int gi = 0; gi < 4; gi++) {
        int row = dir*2048 + gi*512 + hd;
        float v = xg[((long)s*BA + b)*4096 + row];
        if (step > 0) {
#pragma unroll
            for (int sl = 0; sl < 8; sl++)
                v += part[((long)sl*4096 + row)*16 + b];
        }
        g[gi] = v;
    }
    int ci = dir*(BA*HD2) + b*HD2 + hd;
    float cc = step ? c[ci] : 0.f;
    float cn = sigf(g[1])*cc + sigf(g[0])*tanhf(g[2]);
    float hn = sigf(g[3])*tanhf(cn);
    c[ci] = cn; hout[ci] = hn;
    y[((long)s*BA + b)*HID + dir*512 + hd] = hn;
    if (step == SL-1) {
        h0l[b*HID + dir*512 + hd] = hn;
        c0l[b*HID + dir*512 + hd] = cn;
    }
}

// ---------------- decoder cell ----------------
__global__ __launch_bounds__(256) void dec_cell_k(
    const float* __restrict__ part, const float* __restrict__ pre,
    const float* __restrict__ b1, const float* __restrict__ b2,
    float* __restrict__ c, float* __restrict__ hout)
{
    int idx = blockIdx.x*256 + threadIdx.x;
    int b = idx & 15, hd = idx >> 4;
    float g[4];
#pragma unroll
    for (int gi = 0; gi < 4; gi++) {
        int row = gi*HID + hd;
        float v;
        if (pre) v = pre[(long)b*4096 + row];
        else     v = b1[row] + b2[row];
#pragma unroll
        for (int sl = 0; sl < 8; sl++)
            v += part[((long)sl*4096 + row)*16 + b];
        g[gi] = v;
    }
    int ci = b*HID + hd;
    float cc = c[ci];
    float cn = sigf(g[1])*cc + sigf(g[0])*tanhf(g[2]);
    c[ci] = cn;
    hout[ci] = sigf(g[3])*tanhf(cn);
}

// ---------------- h_tilde cell: tanh(sum partials + bias) -------------------
__global__ __launch_bounds__(256) void htanh_k(
    const float* __restrict__ part, const float* __restrict__ bc,
    float* __restrict__ htl, float* __restrict__ hbt, int t)
{
    int idx = blockIdx.x*256 + threadIdx.x;
    int b = idx & 15, hd = idx >> 4;
    float v = bc[hd];
#pragma unroll
    for (int sl = 0; sl < 8; sl++)
        v += part[((long)sl*1024 + hd)*16 + b];
    float h = tanhf(v);
    htl[b*HID + hd] = h;
    hbt[((long)b*TL + t)*HID + hd] = h;
}

// ---------------- attention ----------------
__global__ __launch_bounds__(256) void attn_k(
    const float* __restrict__ h3, const float* __restrict__ hA,
    const float* __restrict__ hsrc, float* __restrict__ ctx)
{
    __shared__ float h3s[HID];
    __shared__ float sc[SL];
    int b = blockIdx.x, tid = threadIdx.x;
    for (int i = tid; i < HID; i += 256) h3s[i] = h3[b*HID + i];
    __syncthreads();
    int w = tid >> 5, lane = tid & 31;
    for (int s = w; s < SL; s += 8) {
        const float* hp = hA + ((long)s*BA + b)*HID;
        float p = 0.f;
        for (int k = lane; k < HID; k += 32) p = fmaf(h3s[k], hp[k], p);
#pragma unroll
        for (int o = 16; o > 0; o >>= 1) p += __shfl_xor_sync(0xffffffffu, p, o);
        if (lane == 0) sc[s] = p;
    }
    __syncthreads();
    if (tid == 0) {
        float mx = sc[0];
        for (int s = 1; s < SL; s++) mx = fmaxf(mx, sc[s]);
        float sum = 0.f;
        for (int s = 0; s < SL; s++) { sc[s] = expf(sc[s]-mx); sum += sc[s]; }
        float inv = 1.f/sum;
        for (int s = 0; s < SL; s++) sc[s] *= inv;
    }
    __syncthreads();
    float4 acc = make_float4(0,0,0,0);
    int k = tid*4;
    for (int s = 0; s < SL; s++) {
        float ws = sc[s];
        float4 v = *(const float4*)(hsrc + ((long)s*BA + b)*HID + k);
        acc.x = fmaf(ws, v.x, acc.x); acc.y = fmaf(ws, v.y, acc.y);
        acc.z = fmaf(ws, v.z, acc.z); acc.w = fmaf(ws, v.w, acc.w);
    }
    *(float4*)(ctx + b*HID + k) = acc;
}

// ---------------- log-softmax ----------------
__global__ __launch_bounds__(256) void lsm_k(float* __restrict__ out)
{
    __shared__ float red[256];
    long m = blockIdx.x;
    float* row = out + m*VOUT;
    int tid = threadIdx.x;
    float mx = -1e30f;
    for (int i = tid; i < VOUT/4; i += 256) {
        float4 v = *(const float4*)(row + i*4);
        mx = fmaxf(mx, fmaxf(fmaxf(v.x, v.y), fmaxf(v.z, v.w)));
    }
    red[tid] = mx; __syncthreads();
    for (int o = 128; o > 0; o >>= 1) { if (tid < o) red[tid] = fmaxf(red[tid], red[tid+o]); __syncthreads(); }
    mx = red[0]; __syncthreads();
    float sum = 0.f;
    for (int i = tid; i < VOUT/4; i += 256) {
        float4 v = *(const float4*)(row + i*4);
        sum += expf(v.x-mx)+expf(v.y-mx)+expf(v.z-mx)+expf(v.w-mx);
    }
    red[tid] = sum; __syncthreads();
    for (int o = 128; o > 0; o >>= 1) { if (tid < o) red[tid] += red[tid+o]; __syncthreads(); }
    float lse = mx + logf(red[0]);
    for (int i = tid; i < VOUT/4; i += 256) {
        float4 v = *(const float4*)(row + i*4);
        v.x -= lse; v.y -= lse; v.z -= lse; v.w -= lse;
        *(float4*)(row + i*4) = v;
    }
}

static float* sym(const void* s){ void* p = nullptr; cudaGetSymbolAddress(&p, s); return (float*)p; }

extern "C" void kernel_launch(void* const* d_in, const int* in_sizes, int n_in,
                              void* d_out, int out_size)
{
    const int*   src   = (const int*)  d_in[0];
    const int*   tgt   = (const int*)  d_in[1];
    const float* embS  = (const float*)d_in[2];
    const float* embD  = (const float*)d_in[3];
    const float* eWih  = (const float*)d_in[4];
    const float* eWhh  = (const float*)d_in[5];
    const float* ebih  = (const float*)d_in[6];
    const float* ebhh  = (const float*)d_in[7];
    const float* d0Wih = (const float*)d_in[8];
    const float* d0Whh = (const float*)d_in[9];
    const float* d0bih = (const float*)d_in[10];
    const float* d0bhh = (const float*)d_in[11];
    const float* dWih  = (const float*)d_in[12];
    const float* dWhh  = (const float*)d_in[13];
    const float* dbih  = (const float*)d_in[14];
    const float* dbhh  = (const float*)d_in[15];
    const float* Wattn = (const float*)d_in[16];
    const float* Wcat  = (const float*)d_in[17];
    const float* bcat  = (const float*)d_in[18];
    const float* Wout  = (const float*)d_in[19];
    const float* bout  = (const float*)d_in[20];
    float* out = (float*)d_out;

    float* encx = sym(g_encx);  float* ency = sym(g_ency);
    float* encxg = sym(g_encxg);
    float* ehA = sym(g_enchA);  float* ehB = sym(g_enchB);
    float* ecc = sym(g_encc);
    float* h0 = sym(g_h0);      float* c0 = sym(g_c0);
    float* demb = sym(g_demb);  float* pre0 = sym(g_pre0);
    float* dhA = sym(g_dhA);    float* dhB = sym(g_dhB);
    float* dc  = sym(g_dc);
    float* htl = sym(g_htl);    float* ctx = sym(g_ctx);
    float* hAp = sym(g_hA);     float* hbt = sym(g_hbt);
    float* part = sym(g_part);

    // ---- encoder ----
    embed_k<<<dim3(SL, BA), 256>>>(src, embS, encx, SL);
    float* xin = encx; float* yout = ency;
    for (int l = 0; l < NL; l++) {
        gemm_k<<<dim3(32, 7), 256>>>(xin, HID, eWih + (long)l*4096*1024, 1024, 1,
                                     ebih + l*4096, ebhh + l*4096, encxg, 4096,
                                     SL*BA, 4096, 1024);
        float* hi = ehA; float* ho = ehB;
        const float* Whh = eWhh + (long)l*4096*512;
        for (int st = 0; st < SL; st++) {
            if (st > 0)
                mm_k<<<256, 256>>>(Whh, 512, 0, hi, 512,
                                   nullptr, 0, hi + BA*HD2, 512,
                                   1, 64, part, 4096);
            enc_cell_k<<<64, 256>>>(part, encxg, ecc, ho, yout,
                                    h0 + (long)l*BA*HID, c0 + (long)l*BA*HID, st);
            float* tmp = hi; hi = ho; ho = tmp;
        }
        float* t = xin; xin = yout; yout = t;
    }
    float* hsrc = xin;

    // ---- decoder precompute ----
    embed_k<<<dim3(TL, BA), 256>>>(tgt, embD, demb, TL);
    gemm_k<<<dim3(32, 7), 256>>>(demb, HID, d0Wih, 2048, 1, d0bih, d0bhh,
                                 pre0, 4096, TL*BA, 4096, 1024);
    gemm_k<<<dim3(8, 7), 256>>>(hsrc, HID, Wattn, 1024, 0, nullptr, nullptr,
                                hAp, HID, SL*BA, 1024, 1024);
    copy_k<<<(NL*BA*HID+255)/256, 256>>>(dhA, h0, NL*BA*HID);
    copy_k<<<(NL*BA*HID+255)/256, 256>>>(dc, c0, NL*BA*HID);
    zero_k<<<(BA*HID+255)/256, 256>>>(htl, BA*HID);

    // ---- decoder loop ----
    float* hi = dhA; float* ho = dhB;
    for (int t = 0; t < TL; t++) {
        // layer 0: gates = htl@Wih_h^T + h_prev0@Whh^T (+ pre0 incl. emb & biases)
        mm_k<<<256, 256>>>(d0Wih + 1024, 2048, 1024, htl, HID,
                           d0Whh, HID, hi, HID, 0, 256, part, 4096);
        dec_cell_k<<<64, 256>>>(part, pre0 + (long)t*BA*4096, nullptr, nullptr,
                                dc, ho);
        for (int i = 0; i < NL-1; i++) {
            mm_k<<<256, 256>>>(dWih + (long)i*4096*1024, 1024, 1024,
                               ho + (long)i*BA*HID, HID,
                               dWhh + (long)i*4096*1024, HID,
                               hi + (long)(i+1)*BA*HID, HID, 0, 256, part, 4096);
            dec_cell_k<<<64, 256>>>(part, nullptr, dbih + i*4096, dbhh + i*4096,
                                    dc + (long)(i+1)*BA*HID, ho + (long)(i+1)*BA*HID);
        }
        attn_k<<<BA, 256>>>(ho + (long)3*BA*HID, hAp, hsrc, ctx);
        mm_k<<<64, 256>>>(Wcat, 2048, 1024, ho + (long)3*BA*HID, HID,
                          Wcat + 1024, 2048, ctx, HID, 0, 256, part, 1024);
        htanh_k<<<64, 256>>>(part, bcat, htl, hbt, t);
        float* tmp = hi; hi = ho; ho = tmp;
    }

    // ---- generator ----
    gemm_k<<<dim3(250, 7), 256>>>(hbt, HID, Wout, 1024, 1, bout, nullptr,
                                  out, VOUT, BA*TL, VOUT, 1024);
    lsm_k<<<BA*TL, 256>>>(out);
}

// round 6
// speedup vs baseline: 1.8518x; 1.0550x over previous
#include <cuda_runtime.h>
#include <cuda_bf16.h>
#include <math.h>

#define SL 50
#define TL 50
#define BA 16
#define HID 1024
#define HD2 512
#define NL 4
#define VOUT 32000

__device__ __align__(16) float g_encx [SL*BA*HID];
__device__ __align__(16) float g_ency [SL*BA*HID];
__device__ __align__(16) float g_encxg[SL*BA*4096];
__device__ __align__(16) float g_enchA[2*BA*HD2];
__device__ __align__(16) float g_enchB[2*BA*HD2];
__device__ __align__(16) float g_encc [2*BA*HD2];
__device__ __align__(16) float g_h0   [NL*BA*HID];
__device__ __align__(16) float g_c0   [NL*BA*HID];
__device__ __align__(16) float g_demb [TL*BA*HID];
__device__ __align__(16) float g_pre0 [TL*BA*4096];
__device__ __align__(16) float g_dhA  [NL*BA*HID];
__device__ __align__(16) float g_dhB  [NL*BA*HID];
__device__ __align__(16) float g_dc   [NL*BA*HID];
__device__ __align__(16) float g_htl  [BA*HID];
__device__ __align__(16) float g_ctx  [BA*HID];
__device__ __align__(16) float g_hA   [SL*BA*HID];
__device__ __align__(16) float g_hbt  [TL*BA*HID];   // [t][b][H]
__device__ __align__(16) float g_part [16*4096*16];
// bf16 weight cache: [d0Wih_h | d0Whh | dWih(3) | dWhh(3) | Wc1 | Wc2]
#define OFF_W0H 0L
#define OFF_W0R 4194304L
#define OFF_WIH 8388608L
#define OFF_WHH 20971520L
#define OFF_WC1 33554432L
#define OFF_WC2 34603008L
__device__ __align__(16) __nv_bfloat16 g_wbf[35651584];

__device__ __forceinline__ float sigf(float x){ return 1.f/(1.f+expf(-x)); }

__global__ void embed_k(const int* __restrict__ idx, const float* __restrict__ W,
                        float* __restrict__ out, int slen){
    int s = blockIdx.x, b = blockIdx.y;
    long tok = idx[b*slen + s];
    const float4* sp = (const float4*)(W + tok*1024);
    float4* dp = (float4*)(out + ((long)s*BA + b)*1024);
    for (int i = threadIdx.x; i < 256; i += blockDim.x) dp[i] = sp[i];
}

// decoder state init: dh=h0, dc=c0, htl=0
__global__ void dinit_k(float* __restrict__ dh, const float* __restrict__ h0,
                        float* __restrict__ dcc, const float* __restrict__ c0,
                        float* __restrict__ htl){
    int i = blockIdx.x*256 + threadIdx.x;
    dh[i] = h0[i];
    dcc[i] = c0[i];
    if (i < BA*HID) htl[i] = 0.f;
}

// fp32 -> bf16 weight conversion, grid-stride
__global__ void cvt_k(__nv_bfloat16* __restrict__ dst, const float* __restrict__ src,
                      int srcld, int col0, int ncols, long total){
    long stride = (long)gridDim.x*blockDim.x;
    for (long i = (long)blockIdx.x*blockDim.x + threadIdx.x; i < total; i += stride){
        long r = i / ncols, cc = i - r*ncols;
        dst[i] = __float2bfloat16(src[r*srcld + col0 + cc]);
    }
}

// ---------------- big tiled GEMM ----------------
// scat!=0: output row for local row m = (m&15)*TL + t0 + (m>>4)   (hbt [t][b] -> out [b][t])
__global__ __launch_bounds__(256) void gemm_k(
    const float* __restrict__ A, int lda,
    const float* __restrict__ B, int ldb, int transB,
    const float* __restrict__ b1, const float* __restrict__ b2,
    float* __restrict__ C, int ldc, int M, int N, int K, int scat, int t0)
{
    __shared__ float As[16][132];
    __shared__ float Bs[16][132];
    int m0 = blockIdx.y*128, n0 = blockIdx.x*128;
    int tid = threadIdx.x, tx = tid & 15, ty = tid >> 4;
    float acc[8][8];
#pragma unroll
    for (int i = 0; i < 8; i++)
#pragma unroll
        for (int j = 0; j < 8; j++) acc[i][j] = 0.f;

    for (int k0 = 0; k0 < K; k0 += 16) {
#pragma unroll
        for (int i = 0; i < 2; i++) {
            int e = tid + i*256, m = e >> 2, kq = e & 3;
            float4 v = make_float4(0,0,0,0);
            if (m0 + m < M) v = *(const float4*)(A + (long)(m0+m)*lda + k0 + kq*4);
            As[kq*4+0][m]=v.x; As[kq*4+1][m]=v.y; As[kq*4+2][m]=v.z; As[kq*4+3][m]=v.w;
        }
        if (transB) {
#pragma unroll
            for (int i = 0; i < 2; i++) {
                int e = tid + i*256, n = e >> 2, kq = e & 3;
                float4 v = *(const float4*)(B + (long)(n0+n)*ldb + k0 + kq*4);
                Bs[kq*4+0][n]=v.x; Bs[kq*4+1][n]=v.y; Bs[kq*4+2][n]=v.z; Bs[kq*4+3][n]=v.w;
            }
        } else {
#pragma unroll
            for (int i = 0; i < 2; i++) {
                int e = tid + i*256, kk = e >> 5, nq = e & 31;
                *(float4*)&Bs[kk][nq*4] = *(const float4*)(B + (long)(k0+kk)*ldb + n0 + nq*4);
            }
        }
        __syncthreads();
#pragma unroll
        for (int kk = 0; kk < 16; kk++) {
            float a[8], bv[8];
            *(float4*)&a[0] = *(float4*)&As[kk][ty*8];
            *(float4*)&a[4] = *(float4*)&As[kk][ty*8+4];
            *(float4*)&bv[0] = *(float4*)&Bs[kk][tx*8];
            *(float4*)&bv[4] = *(float4*)&Bs[kk][tx*8+4];
#pragma unroll
            for (int i = 0; i < 8; i++)
#pragma unroll
                for (int j = 0; j < 8; j++) acc[i][j] = fmaf(a[i], bv[j], acc[i][j]);
        }
        __syncthreads();
    }
#pragma unroll
    for (int i = 0; i < 8; i++) {
        int m = m0 + ty*8 + i;
        if (m < M) {
            long crow = scat ? ((long)(m & 15)*TL + t0 + (m >> 4)) : (long)m;
            float* Cr = C + crow*ldc + n0 + tx*8;
#pragma unroll
            for (int j = 0; j < 8; j++) {
                int n = n0 + tx*8 + j;
                float v = acc[i][j];
                if (b1) v += b1[n];
                if (b2) v += b2[n];
                Cr[j] = v;
            }
        }
    }
}

// ------- fused encoder step: full-K matvec + LSTM cell, both dirs, 1 kernel -
// grid 64: dir = bid>>5, 16 hd per block. 256 threads.
__global__ __launch_bounds__(256) void enc_fused_k(
    const float* __restrict__ Whh, const float* __restrict__ xg,
    const float* __restrict__ hin, float* __restrict__ hout,
    float* __restrict__ c, float* __restrict__ y,
    float* __restrict__ h0l, float* __restrict__ c0l, int step)
{
    __shared__ __align__(16) float hs[512][20];
    __shared__ float sg[64][17];
    int tid = threadIdx.x;
    int dir = blockIdx.x >> 5, hg = blockIdx.x & 31;
    int s = dir ? (SL-1-step) : step;
    int r = tid >> 2, q = tid & 3;        // r = g*16+j, q = batch quad
    float a0=0,a1=0,a2=0,a3=0;

    if (step > 0) {
        const float* hsrc = hin + dir*(BA*HD2);
#pragma unroll
        for (int i = 0; i < 32; i++) {
            int e = tid + i*256;
            hs[e & 511][e >> 9] = hsrc[e];
        }
        __syncthreads();
        int g = r >> 4, j = r & 15;
        const float* wr = Whh + ((long)dir*2048 + g*512 + hg*16 + j) * 512;
#pragma unroll 4
        for (int k = 0; k < 512; k += 8) {
            float w8[8];
            *(float4*)&w8[0] = *(const float4*)(wr + k);
            *(float4*)&w8[4] = *(const float4*)(wr + k + 4);
#pragma unroll
            for (int kk = 0; kk < 8; kk++) {
                float4 xv = *(const float4*)&hs[k+kk][q*4];
                a0 = fmaf(w8[kk], xv.x, a0);
                a1 = fmaf(w8[kk], xv.y, a1);
                a2 = fmaf(w8[kk], xv.z, a2);
                a3 = fmaf(w8[kk], xv.w, a3);
            }
        }
    }
    sg[r][q*4+0]=a0; sg[r][q*4+1]=a1; sg[r][q*4+2]=a2; sg[r][q*4+3]=a3;
    __syncthreads();

    int j = tid >> 4, b = tid & 15;
    int hd = hg*16 + j;
    long xb = ((long)s*BA + b)*4096 + dir*2048 + hd;
    float gi = sg[j     ][b] + xg[xb];
    float gf = sg[16 + j][b] + xg[xb + 512];
    float gg = sg[32 + j][b] + xg[xb + 1024];
    float go = sg[48 + j][b] + xg[xb + 1536];
    int ci = dir*(BA*HD2) + b*HD2 + hd;
    float cc = step ? c[ci] : 0.f;
    float cn = sigf(gf)*cc + sigf(gi)*tanhf(gg);
    float hn = sigf(go)*tanhf(cn);
    c[ci] = cn; hout[ci] = hn;
    y[((long)s*BA + b)*HID + dir*512 + hd] = hn;
    if (step == SL-1) {
        h0l[b*HID + dir*512 + hd] = hn;
        c0l[b*HID + dir*512 + hd] = cn;
    }
}

// -------- decoder matvec: bf16 weights, fp32 x/accum, double-buffered -------
__global__ __launch_bounds__(256) void mmbf_k(
    const __nv_bfloat16* __restrict__ W1, const __nv_bfloat16* __restrict__ W2,
    const float* __restrict__ x1, const float* __restrict__ x2,
    float* __restrict__ part, int rtot)
{
    __shared__ __align__(16) float Wt[2][32][130];
    __shared__ __align__(16) float xs[2][32][20];
    int tid = threadIdx.x;
    int slice = blockIdx.x & 15, rg = blockIdx.x >> 4;
    int r0 = rg*128, k0 = slice*128;
    const __nv_bfloat16* W; const float* x; int ko;
    if (k0 < 1024) { W = W1; x = x1; ko = k0; }
    else           { W = W2; x = x2; ko = k0 - 1024; }
    int rp = tid >> 2, rq = tid & 3;

    float4 wreg[2];
    float  xreg[2];
    float a00=0,a01=0,a02=0,a03=0,a10=0,a11=0,a12=0,a13=0;

    auto ldg = [&](int kt){
#pragma unroll
        for (int i = 0; i < 2; i++) {
            int e = tid + i*256; int row = e >> 2, q = e & 3;
            wreg[i] = *(const float4*)(W + (long)(r0+row)*1024 + ko + kt + q*8);
        }
#pragma unroll
        for (int i = 0; i < 2; i++) {
            int e = tid + i*256; int b = e >> 5, kk = e & 31;
            xreg[i] = x[b*1024 + ko + kt + kk];
        }
    };
    auto sts = [&](int buf){
#pragma unroll
        for (int i = 0; i < 2; i++) {
            int e = tid + i*256; int row = e >> 2, q = e & 3;
            const __nv_bfloat162* p = (const __nv_bfloat162*)&wreg[i];
#pragma unroll
            for (int j = 0; j < 4; j++) {
                float2 f = __bfloat1622float2(p[j]);
                Wt[buf][q*8+2*j  ][row] = f.x;
                Wt[buf][q*8+2*j+1][row] = f.y;
            }
        }
#pragma unroll
        for (int i = 0; i < 2; i++) {
            int e = tid + i*256; int b = e >> 5, kk = e & 31;
            xs[buf][kk][b] = xreg[i];
        }
    };
    auto comp = [&](int buf){
#pragma unroll
        for (int kk = 0; kk < 32; kk++) {
            float2 w  = *(const float2*)&Wt[buf][kk][2*rp];
            float4 xv = *(const float4*)&xs[buf][kk][4*rq];
            a00 = fmaf(w.x, xv.x, a00); a01 = fmaf(w.x, xv.y, a01);
            a02 = fmaf(w.x, xv.z, a02); a03 = fmaf(w.x, xv.w, a03);
            a10 = fmaf(w.y, xv.x, a10); a11 = fmaf(w.y, xv.y, a11);
            a12 = fmaf(w.y, xv.z, a12); a13 = fmaf(w.y, xv.w, a13);
        }
    };

    ldg(0); sts(0); __syncthreads();
#pragma unroll
    for (int t = 0; t < 4; t++) {
        if (t < 3) ldg((t+1)*32);
        comp(t & 1);
        if (t < 3) { sts((t+1) & 1); __syncthreads(); }
    }
    float* p = part + ((long)slice*rtot + r0 + 2*rp)*16 + 4*rq;
    *(float4*)p        = make_float4(a00,a01,a02,a03);
    *(float4*)(p + 16) = make_float4(a10,a11,a12,a13);
}

// ---------------- decoder cell ----------------
__global__ __launch_bounds__(256) void dec_cell_k(
    const float* __restrict__ part, const float* __restrict__ pre,
    const float* __restrict__ b1, const float* __restrict__ b2,
    float* __restrict__ c, float* __restrict__ hout)
{
    int idx = blockIdx.x*256 + threadIdx.x;
    int b = idx & 15, hd = idx >> 4;
    float g[4];
#pragma unroll
    for (int gi = 0; gi < 4; gi++) {
        int row = gi*HID + hd;
        float v;
        if (pre) v = pre[(long)b*4096 + row];
        else     v = b1[row] + b2[row];
#pragma unroll
        for (int sl = 0; sl < 16; sl++)
            v += part[((long)sl*4096 + row)*16 + b];
        g[gi] = v;
    }
    int ci = b*HID + hd;
    float cc = c[ci];
    float cn = sigf(g[1])*cc + sigf(g[0])*tanhf(g[2]);
    c[ci] = cn;
    hout[ci] = sigf(g[3])*tanhf(cn);
}

// ---------------- h_tilde cell ----------------
__global__ __launch_bounds__(256) void htanh_k(
    const float* __restrict__ part, const float* __restrict__ bc,
    float* __restrict__ htl, float* __restrict__ hbt, int t)
{
    int idx = blockIdx.x*256 + threadIdx.x;
    int b = idx & 15, hd = idx >> 4;
    float v = bc[hd];
#pragma unroll
    for (int sl = 0; sl < 16; sl++)
        v += part[((long)sl*1024 + hd)*16 + b];
    float h = tanhf(v);
    htl[b*HID + hd] = h;
    hbt[((long)t*BA + b)*HID + hd] = h;   // [t][b][H]
}

// ---------------- attention ----------------
__global__ __launch_bounds__(256) void attn_k(
    const float* __restrict__ h3, const float* __restrict__ hA,
    const float* __restrict__ hsrc, float* __restrict__ ctx)
{
    __shared__ float h3s[HID];
    __shared__ float sc[SL];
    int b = blockIdx.x, tid = threadIdx.x;
    for (int i = tid; i < HID; i += 256) h3s[i] = h3[b*HID + i];
    __syncthreads();
    int w = tid >> 5, lane = tid & 31;
    for (int s = w; s < SL; s += 8) {
        const float* hp = hA + ((long)s*BA + b)*HID;
        float p = 0.f;
        for (int k = lane; k < HID; k += 32) p = fmaf(h3s[k], hp[k], p);
#pragma unroll
        for (int o = 16; o > 0; o >>= 1) p += __shfl_xor_sync(0xffffffffu, p, o);
        if (lane == 0) sc[s] = p;
    }
    __syncthreads();
    if (tid == 0) {
        float mx = sc[0];
        for (int s = 1; s < SL; s++) mx = fmaxf(mx, sc[s]);
        float sum = 0.f;
        for (int s = 0; s < SL; s++) { sc[s] = expf(sc[s]-mx); sum += sc[s]; }
        float inv = 1.f/sum;
        for (int s = 0; s < SL; s++) sc[s] *= inv;
    }
    __syncthreads();
    float4 acc = make_float4(0,0,0,0);
    int k = tid*4;
    for (int s = 0; s < SL; s++) {
        float ws = sc[s];
        float4 v = *(const float4*)(hsrc + ((long)s*BA + b)*HID + k);
        acc.x = fmaf(ws, v.x, acc.x); acc.y = fmaf(ws, v.y, acc.y);
        acc.z = fmaf(ws, v.z, acc.z); acc.w = fmaf(ws, v.w, acc.w);
    }
    *(float4*)(ctx + b*HID + k) = acc;
}

// ---------------- log-softmax ----------------
__global__ __launch_bounds__(256) void lsm_k(float* __restrict__ out)
{
    __shared__ float red[256];
    long m = blockIdx.x;
    float* row = out + m*VOUT;
    int tid = threadIdx.x;
    float mx = -1e30f;
    for (int i = tid; i < VOUT/4; i += 256) {
        float4 v = *(const float4*)(row + i*4);
        mx = fmaxf(mx, fmaxf(fmaxf(v.x, v.y), fmaxf(v.z, v.w)));
    }
    red[tid] = mx; __syncthreads();
    for (int o = 128; o > 0; o >>= 1) { if (tid < o) red[tid] = fmaxf(red[tid], red[tid+o]); __syncthreads(); }
    mx = red[0]; __syncthreads();
    float sum = 0.f;
    for (int i = tid; i < VOUT/4; i += 256) {
        float4 v = *(const float4*)(row + i*4);
        sum += expf(v.x-mx)+expf(v.y-mx)+expf(v.z-mx)+expf(v.w-mx);
    }
    red[tid] = sum; __syncthreads();
    for (int o = 128; o > 0; o >>= 1) { if (tid < o) red[tid] += red[tid+o]; __syncthreads(); }
    float lse = mx + logf(red[0]);
    for (int i = tid; i < VOUT/4; i += 256) {
        float4 v = *(const float4*)(row + i*4);
        v.x -= lse; v.y -= lse; v.z -= lse; v.w -= lse;
        *(float4*)(row + i*4) = v;
    }
}

static float* sym(const void* s){ void* p = nullptr; cudaGetSymbolAddress(&p, s); return (float*)p; }

extern "C" void kernel_launch(void* const* d_in, const int* in_sizes, int n_in,
                              void* d_out, int out_size)
{
    const int*   src   = (const int*)  d_in[0];
    const int*   tgt   = (const int*)  d_in[1];
    const float* embS  = (const float*)d_in[2];
    const float* embD  = (const float*)d_in[3];
    const float* eWih  = (const float*)d_in[4];
    const float* eWhh  = (const float*)d_in[5];
    const float* ebih  = (const float*)d_in[6];
    const float* ebhh  = (const float*)d_in[7];
    const float* d0Wih = (const float*)d_in[8];
    const float* d0Whh = (const float*)d_in[9];
    const float* d0bih = (const float*)d_in[10];
    const float* d0bhh = (const float*)d_in[11];
    const float* dWih  = (const float*)d_in[12];
    const float* dWhh  = (const float*)d_in[13];
    const float* dbih  = (const float*)d_in[14];
    const float* dbhh  = (const float*)d_in[15];
    const float* Wattn = (const float*)d_in[16];
    const float* Wcat  = (const float*)d_in[17];
    const float* bcat  = (const float*)d_in[18];
    const float* Wout  = (const float*)d_in[19];
    const float* bout  = (const float*)d_in[20];
    float* out = (float*)d_out;

    float* encx = sym(g_encx);  float* ency = sym(g_ency);
    float* encxg = sym(g_encxg);
    float* ehA = sym(g_enchA);  float* ehB = sym(g_enchB);
    float* ecc = sym(g_encc);
    float* h0 = sym(g_h0);      float* c0 = sym(g_c0);
    float* demb = sym(g_demb);  float* pre0 = sym(g_pre0);
    float* dhA = sym(g_dhA);    float* dhB = sym(g_dhB);
    float* dc  = sym(g_dc);
    float* htl = sym(g_htl);    float* ctx = sym(g_ctx);
    float* hAp = sym(g_hA);     float* hbt = sym(g_hbt);
    float* part = sym(g_part);
    __nv_bfloat16* wbf = (__nv_bfloat16*)sym(g_wbf);

    // second stream + events for generator overlap (created once; first call
    // is the uncaptured correctness run, so any driver allocs pre-date the
    // harness's pre-capture baseline)
    static cudaStream_t s2 = nullptr;
    static cudaEvent_t evc[8];
    if (!s2) {
        cudaStreamCreateWithFlags(&s2, cudaStreamNonBlocking);
        for (int i = 0; i < 8; i++)
            cudaEventCreateWithFlags(&evc[i], cudaEventDisableTiming);
    }

    // ---- bf16 weight conversion (decoder recurrent path) ----
    {
        long n1 = 4194304L, n3 = 12582912L, nc = 1048576L;
        cvt_k<<<1024, 256>>>(wbf + OFF_W0H, d0Wih, 2048, 1024, 1024, n1);
        cvt_k<<<1024, 256>>>(wbf + OFF_W0R, d0Whh, 1024, 0, 1024, n1);
        cvt_k<<<1024, 256>>>(wbf + OFF_WIH, dWih, 1024, 0, 1024, n3);
        cvt_k<<<1024, 256>>>(wbf + OFF_WHH, dWhh, 1024, 0, 1024, n3);
        cvt_k<<<1024, 256>>>(wbf + OFF_WC1, Wcat, 2048, 0, 1024, nc);
        cvt_k<<<1024, 256>>>(wbf + OFF_WC2, Wcat, 2048, 1024, 1024, nc);
    }

    // ---- encoder ----
    embed_k<<<dim3(SL, BA), 256>>>(src, embS, encx, SL);
    float* xin = encx; float* yout = ency;
    for (int l = 0; l < NL; l++) {
        gemm_k<<<dim3(32, 7), 256>>>(xin, HID, eWih + (long)l*4096*1024, 1024, 1,
                                     ebih + l*4096, ebhh + l*4096, encxg, 4096,
                                     SL*BA, 4096, 1024, 0, 0);
        float* hi = ehA; float* ho = ehB;
        const float* Whh = eWhh + (long)l*4096*512;
        for (int st = 0; st < SL; st++) {
            enc_fused_k<<<64, 256>>>(Whh, encxg, hi, ho, ecc, yout,
                                     h0 + (long)l*BA*HID, c0 + (long)l*BA*HID, st);
            float* tmp = hi; hi = ho; ho = tmp;
        }
        float* t = xin; xin = yout; yout = t;
    }
    float* hsrc = xin;

    // ---- decoder precompute ----
    embed_k<<<dim3(TL, BA), 256>>>(tgt, embD, demb, TL);
    gemm_k<<<dim3(32, 7), 256>>>(demb, HID, d0Wih, 2048, 1, d0bih, d0bhh,
                                 pre0, 4096, TL*BA, 4096, 1024, 0, 0);
    gemm_k<<<dim3(8, 7), 256>>>(hsrc, HID, Wattn, 1024, 0, nullptr, nullptr,
                                hAp, HID, SL*BA, 1024, 1024, 0, 0);
    dinit_k<<<NL*BA*HID/256, 256>>>(dhA, h0, dc, c0, htl);

    // ---- decoder loop with overlapped generator chunks ----
    float* hi = dhA; float* ho = dhB;
    for (int t = 0; t < TL; t++) {
        mmbf_k<<<512, 256>>>(wbf + OFF_W0H, wbf + OFF_W0R, htl, hi, part, 4096);
        dec_cell_k<<<64, 256>>>(part, pre0 + (long)t*BA*4096, nullptr, nullptr,
                                dc, ho);
        for (int i = 0; i < NL-1; i++) {
            mmbf_k<<<512, 256>>>(wbf + OFF_WIH + (long)i*4194304,
                                 wbf + OFF_WHH + (long)i*4194304,
                                 ho + (long)i*BA*HID,
                                 hi + (long)(i+1)*BA*HID, part, 4096);
            dec_cell_k<<<64, 256>>>(part, nullptr, dbih + i*4096, dbhh + i*4096,
                                    dc + (long)(i+1)*BA*HID, ho + (long)(i+1)*BA*HID);
        }
        attn_k<<<BA, 256>>>(ho + (long)3*BA*HID, hAp, hsrc, ctx);
        mmbf_k<<<128, 256>>>(wbf + OFF_WC1, wbf + OFF_WC2,
                             ho + (long)3*BA*HID, ctx, part, 1024);
        htanh_k<<<64, 256>>>(part, bcat, htl, hbt, t);

        if ((t & 7) == 7 || t == TL-1) {
            int ci = t >> 3;                 // 0..6
            int t0 = ci*8;
            int nt = (t0 + 8 <= TL) ? 8 : (TL - t0);
            int rows = nt*BA;
            cudaEventRecord(evc[ci], 0);
            cudaStreamWaitEvent(s2, evc[ci], 0);
            gemm_k<<<dim3(250, 1), 256, 0, s2>>>(
                hbt + (long)t0*BA*HID, HID, Wout, 1024, 1,
                bout, nullptr, out, VOUT, rows, VOUT, HID, 1, t0);
        }
        float* tmp = hi; hi = ho; ho = tmp;
    }

    // join generator stream, then log-softmax
    cudaEventRecord(evc[7], s2);
    cudaStreamWaitEvent(0, evc[7], 0);
    lsm_k<<<BA*TL, 256>>>(out);
}

// round 7
// speedup vs baseline: 1.9819x; 1.0702x over previous
#include <cuda_runtime.h>
#include <cuda_bf16.h>
#include <math.h>

#define SL 50
#define TL 50
#define BA 16
#define HID 1024
#define HD2 512
#define NL 4
#define VOUT 32000

__device__ __align__(16) float g_encx [SL*BA*HID];
__device__ __align__(16) float g_ency [SL*BA*HID];
__device__ __align__(16) float g_encxg[SL*BA*4096];
__device__ __align__(16) float g_enchA[2*BA*HD2];
__device__ __align__(16) float g_enchB[2*BA*HD2];
__device__ __align__(16) float g_encc [2*BA*HD2];
__device__ __align__(16) float g_h0   [NL*BA*HID];
__device__ __align__(16) float g_c0   [NL*BA*HID];
__device__ __align__(16) float g_demb [TL*BA*HID];
__device__ __align__(16) float g_pre0 [TL*BA*4096];
__device__ __align__(16) float g_dhA  [NL*BA*HID];
__device__ __align__(16) float g_dhB  [NL*BA*HID];
__device__ __align__(16) float g_dc   [NL*BA*HID];
__device__ __align__(16) float g_htl  [BA*HID];
__device__ __align__(16) float g_ctx  [BA*HID];
__device__ __align__(16) float g_hA   [SL*BA*HID];
__device__ __align__(16) float g_hbt  [TL*BA*HID];   // [t][b][H]
__device__ __align__(16) float g_part [16*4096*16];
// bf16 weight cache: [d0Wih_h | d0Whh | dWih(3) | dWhh(3) | Wc1 | Wc2]
#define OFF_W0H 0L
#define OFF_W0R 4194304L
#define OFF_WIH 8388608L
#define OFF_WHH 20971520L
#define OFF_WC1 33554432L
#define OFF_WC2 34603008L
__device__ __align__(16) __nv_bfloat16 g_wbf[35651584];

__device__ __forceinline__ float sigf(float x){ return 1.f/(1.f+expf(-x)); }

__global__ void embed_k(const int* __restrict__ idx, const float* __restrict__ W,
                        float* __restrict__ out, int slen){
    int s = blockIdx.x, b = blockIdx.y;
    long tok = idx[b*slen + s];
    const float4* sp = (const float4*)(W + tok*1024);
    float4* dp = (float4*)(out + ((long)s*BA + b)*1024);
    for (int i = threadIdx.x; i < 256; i += blockDim.x) dp[i] = sp[i];
}

__global__ void dinit_k(float* __restrict__ dh, const float* __restrict__ h0,
                        float* __restrict__ dcc, const float* __restrict__ c0,
                        float* __restrict__ htl){
    int i = blockIdx.x*256 + threadIdx.x;
    dh[i] = h0[i];
    dcc[i] = c0[i];
    if (i < BA*HID) htl[i] = 0.f;
}

__global__ void cvt_k(__nv_bfloat16* __restrict__ dst, const float* __restrict__ src,
                      int srcld, int col0, int ncols, long total){
    long stride = (long)gridDim.x*blockDim.x;
    for (long i = (long)blockIdx.x*blockDim.x + threadIdx.x; i < total; i += stride){
        long r = i / ncols, cc = i - r*ncols;
        dst[i] = __float2bfloat16(src[r*srcld + col0 + cc]);
    }
}

// ---------------- big tiled GEMM ----------------
// scat!=0: output row for local row m = (m&15)*TL + t0 + (m>>4)
__global__ __launch_bounds__(256) void gemm_k(
    const float* __restrict__ A, int lda,
    const float* __restrict__ B, int ldb, int transB,
    const float* __restrict__ b1, const float* __restrict__ b2,
    float* __restrict__ C, int ldc, int M, int N, int K, int scat, int t0)
{
    __shared__ float As[16][132];
    __shared__ float Bs[16][132];
    int m0 = blockIdx.y*128, n0 = blockIdx.x*128;
    int tid = threadIdx.x, tx = tid & 15, ty = tid >> 4;
    float acc[8][8];
#pragma unroll
    for (int i = 0; i < 8; i++)
#pragma unroll
        for (int j = 0; j < 8; j++) acc[i][j] = 0.f;

    for (int k0 = 0; k0 < K; k0 += 16) {
#pragma unroll
        for (int i = 0; i < 2; i++) {
            int e = tid + i*256, m = e >> 2, kq = e & 3;
            float4 v = make_float4(0,0,0,0);
            if (m0 + m < M) v = *(const float4*)(A + (long)(m0+m)*lda + k0 + kq*4);
            As[kq*4+0][m]=v.x; As[kq*4+1][m]=v.y; As[kq*4+2][m]=v.z; As[kq*4+3][m]=v.w;
        }
        if (transB) {
#pragma unroll
            for (int i = 0; i < 2; i++) {
                int e = tid + i*256, n = e >> 2, kq = e & 3;
                float4 v = *(const float4*)(B + (long)(n0+n)*ldb + k0 + kq*4);
                Bs[kq*4+0][n]=v.x; Bs[kq*4+1][n]=v.y; Bs[kq*4+2][n]=v.z; Bs[kq*4+3][n]=v.w;
            }
        } else {
#pragma unroll
            for (int i = 0; i < 2; i++) {
                int e = tid + i*256, kk = e >> 5, nq = e & 31;
                *(float4*)&Bs[kk][nq*4] = *(const float4*)(B + (long)(k0+kk)*ldb + n0 + nq*4);
            }
        }
        __syncthreads();
#pragma unroll
        for (int kk = 0; kk < 16; kk++) {
            float a[8], bv[8];
            *(float4*)&a[0] = *(float4*)&As[kk][ty*8];
            *(float4*)&a[4] = *(float4*)&As[kk][ty*8+4];
            *(float4*)&bv[0] = *(float4*)&Bs[kk][tx*8];
            *(float4*)&bv[4] = *(float4*)&Bs[kk][tx*8+4];
#pragma unroll
            for (int i = 0; i < 8; i++)
#pragma unroll
                for (int j = 0; j < 8; j++) acc[i][j] = fmaf(a[i], bv[j], acc[i][j]);
        }
        __syncthreads();
    }
#pragma unroll
    for (int i = 0; i < 8; i++) {
        int m = m0 + ty*8 + i;
        if (m < M) {
            long crow = scat ? ((long)(m & 15)*TL + t0 + (m >> 4)) : (long)m;
            float* Cr = C + crow*ldc + n0 + tx*8;
#pragma unroll
            for (int j = 0; j < 8; j++) {
                int n = n0 + tx*8 + j;
                float v = acc[i][j];
                if (b1) v += b1[n];
                if (b2) v += b2[n];
                Cr[j] = v;
            }
        }
    }
}

// ------- fused encoder step: full-K matvec + LSTM cell, both dirs ----------
__global__ __launch_bounds__(256) void enc_fused_k(
    const float* __restrict__ Whh, const float* __restrict__ xg,
    const float* __restrict__ hin, float* __restrict__ hout,
    float* __restrict__ c, float* __restrict__ y,
    float* __restrict__ h0l, float* __restrict__ c0l, int step)
{
    __shared__ __align__(16) float hs[512][20];
    __shared__ float sg[64][17];
    int tid = threadIdx.x;
    int dir = blockIdx.x >> 5, hg = blockIdx.x & 31;
    int s = dir ? (SL-1-step) : step;
    int r = tid >> 2, q = tid & 3;
    float a0=0,a1=0,a2=0,a3=0;

    if (step > 0) {
        const float* hsrc = hin + dir*(BA*HD2);
#pragma unroll
        for (int i = 0; i < 32; i++) {
            int e = tid + i*256;
            hs[e & 511][e >> 9] = hsrc[e];
        }
        __syncthreads();
        int g = r >> 4, j = r & 15;
        const float* wr = Whh + ((long)dir*2048 + g*512 + hg*16 + j) * 512;
#pragma unroll 4
        for (int k = 0; k < 512; k += 8) {
            float w8[8];
            *(float4*)&w8[0] = *(const float4*)(wr + k);
            *(float4*)&w8[4] = *(const float4*)(wr + k + 4);
#pragma unroll
            for (int kk = 0; kk < 8; kk++) {
                float4 xv = *(const float4*)&hs[k+kk][q*4];
                a0 = fmaf(w8[kk], xv.x, a0);
                a1 = fmaf(w8[kk], xv.y, a1);
                a2 = fmaf(w8[kk], xv.z, a2);
                a3 = fmaf(w8[kk], xv.w, a3);
            }
        }
    }
    sg[r][q*4+0]=a0; sg[r][q*4+1]=a1; sg[r][q*4+2]=a2; sg[r][q*4+3]=a3;
    __syncthreads();

    int j = tid >> 4, b = tid & 15;
    int hd = hg*16 + j;
    long xb = ((long)s*BA + b)*4096 + dir*2048 + hd;
    float gi = sg[j     ][b] + xg[xb];
    float gf = sg[16 + j][b] + xg[xb + 512];
    float gg = sg[32 + j][b] + xg[xb + 1024];
    float go = sg[48 + j][b] + xg[xb + 1536];
    int ci = dir*(BA*HD2) + b*HD2 + hd;
    float cc = step ? c[ci] : 0.f;
    float cn = sigf(gf)*cc + sigf(gi)*tanhf(gg);
    float hn = sigf(go)*tanhf(cn);
    c[ci] = cn; hout[ci] = hn;
    y[((long)s*BA + b)*HID + dir*512 + hd] = hn;
    if (step == SL-1) {
        h0l[b*HID + dir*512 + hd] = hn;
        c0l[b*HID + dir*512 + hd] = cn;
    }
}

// -------- decoder matvec: single-shot front-batched loads, bf16 smem --------
// K = 2048 in 16 slices of 128 (slices 0-7 -> W1/x1, 8-15 -> W2/x2).
// grid = (rtot/128)*16. Thread tile: 2 rows x 4 batches, full K=128.
__global__ __launch_bounds__(256) void mmbf_k(
    const __nv_bfloat16* __restrict__ W1, const __nv_bfloat16* __restrict__ W2,
    const float* __restrict__ x1, const float* __restrict__ x2,
    float* __restrict__ part, int rtot)
{
    __shared__ __align__(16) __nv_bfloat16 Wt[128][136];  // [row][k]
    __shared__ __align__(16) float xs[128][20];           // [k][batch]
    int tid = threadIdx.x;
    int slice = blockIdx.x & 15, rg = blockIdx.x >> 4;
    int r0 = rg*128, k0 = slice*128;
    const __nv_bfloat16* W; const float* x; int ko;
    if (k0 < 1024) { W = W1; x = x1; ko = k0; }
    else           { W = W2; x = x2; ko = k0 - 1024; }

    // front-batched loads: 8x LDG.128 (W) + 8x LDG.32 (x) per thread
    uint4 wc[8];
    float xr[8];
#pragma unroll
    for (int i = 0; i < 8; i++) {
        int cidx = tid + i*256;               // 2048 chunks of 16B
        int row = cidx >> 4, q = cidx & 15;
        wc[i] = *(const uint4*)(W + (long)(r0+row)*1024 + ko + q*8);
    }
#pragma unroll
    for (int i = 0; i < 8; i++) {
        int e = tid + i*256;                  // 2048 x elements
        int b = e >> 7, kk = e & 127;
        xr[i] = x[b*1024 + ko + kk];
    }
#pragma unroll
    for (int i = 0; i < 8; i++) {
        int cidx = tid + i*256;
        int row = cidx >> 4, q = cidx & 15;
        *(uint4*)&Wt[row][q*8] = wc[i];
    }
#pragma unroll
    for (int i = 0; i < 8; i++) {
        int e = tid + i*256;
        int b = e >> 7, kk = e & 127;
        xs[kk][b] = xr[i];
    }
    __syncthreads();

    int rp = tid >> 2, bq = tid & 3;          // rows 2rp,2rp+1; batches 4bq..
    float a00=0,a01=0,a02=0,a03=0,a10=0,a11=0,a12=0,a13=0;
#pragma unroll 8
    for (int k = 0; k < 128; k += 2) {
        __nv_bfloat162 wa = *(const __nv_bfloat162*)&Wt[2*rp  ][k];
        __nv_bfloat162 wb = *(const __nv_bfloat162*)&Wt[2*rp+1][k];
        float2 fa = __bfloat1622float2(wa);
        float2 fb = __bfloat1622float2(wb);
        float4 x0 = *(const float4*)&xs[k  ][4*bq];
        float4 x1v = *(const float4*)&xs[k+1][4*bq];
        a00 = fmaf(fa.x, x0.x, a00); a01 = fmaf(fa.x, x0.y, a01);
        a02 = fmaf(fa.x, x0.z, a02); a03 = fmaf(fa.x, x0.w, a03);
        a10 = fmaf(fb.x, x0.x, a10); a11 = fmaf(fb.x, x0.y, a11);
        a12 = fmaf(fb.x, x0.z, a12); a13 = fmaf(fb.x, x0.w, a13);
        a00 = fmaf(fa.y, x1v.x, a00); a01 = fmaf(fa.y, x1v.y, a01);
        a02 = fmaf(fa.y, x1v.z, a02); a03 = fmaf(fa.y, x1v.w, a03);
        a10 = fmaf(fb.y, x1v.x, a10); a11 = fmaf(fb.y, x1v.y, a11);
        a12 = fmaf(fb.y, x1v.z, a12); a13 = fmaf(fb.y, x1v.w, a13);
    }
    float* p = part + ((long)slice*rtot + r0 + 2*rp)*16 + 4*bq;
    *(float4*)p        = make_float4(a00,a01,a02,a03);
    *(float4*)(p + 16) = make_float4(a10,a11,a12,a13);
}

// ---------------- decoder cell ----------------
__global__ __launch_bounds__(256) void dec_cell_k(
    const float* __restrict__ part, const float* __restrict__ pre,
    const float* __restrict__ b1, const float* __restrict__ b2,
    float* __restrict__ c, float* __restrict__ hout)
{
    int idx = blockIdx.x*256 + threadIdx.x;
    int b = idx & 15, hd = idx >> 4;
    float g[4];
#pragma unroll
    for (int gi = 0; gi < 4; gi++) {
        int row = gi*HID + hd;
        float v;
        if (pre) v = pre[(long)b*4096 + row];
        else     v = b1[row] + b2[row];
#pragma unroll
        for (int sl = 0; sl < 16; sl++)
            v += part[((long)sl*4096 + row)*16 + b];
        g[gi] = v;
    }
    int ci = b*HID + hd;
    float cc = c[ci];
    float cn = sigf(g[1])*cc + sigf(g[0])*tanhf(g[2]);
    c[ci] = cn;
    hout[ci] = sigf(g[3])*tanhf(cn);
}

// ---------------- h_tilde cell ----------------
__global__ __launch_bounds__(256) void htanh_k(
    const float* __restrict__ part, const float* __restrict__ bc,
    float* __restrict__ htl, float* __restrict__ hbt, int t)
{
    int idx = blockIdx.x*256 + threadIdx.x;
    int b = idx & 15, hd = idx >> 4;
    float v = bc[hd];
#pragma unroll
    for (int sl = 0; sl < 16; sl++)
        v += part[((long)sl*1024 + hd)*16 + b];
    float h = tanhf(v);
    htl[b*HID + hd] = h;
    hbt[((long)t*BA + b)*HID + hd] = h;
}

// ---------------- attention ----------------
__global__ __launch_bounds__(256) void attn_k(
    const float* __restrict__ h3, const float* __restrict__ hA,
    const float* __restrict__ hsrc, float* __restrict__ ctx)
{
    __shared__ float h3s[HID];
    __shared__ float sc[SL];
    int b = blockIdx.x, tid = threadIdx.x;
    for (int i = tid; i < HID; i += 256) h3s[i] = h3[b*HID + i];
    __syncthreads();
    int w = tid >> 5, lane = tid & 31;
    for (int s = w; s < SL; s += 8) {
        const float* hp = hA + ((long)s*BA + b)*HID;
        float p = 0.f;
        for (int k = lane; k < HID; k += 32) p = fmaf(h3s[k], hp[k], p);
#pragma unroll
        for (int o = 16; o > 0; o >>= 1) p += __shfl_xor_sync(0xffffffffu, p, o);
        if (lane == 0) sc[s] = p;
    }
    __syncthreads();
    if (tid == 0) {
        float mx = sc[0];
        for (int s = 1; s < SL; s++) mx = fmaxf(mx, sc[s]);
        float sum = 0.f;
        for (int s = 0; s < SL; s++) { sc[s] = expf(sc[s]-mx); sum += sc[s]; }
        float inv = 1.f/sum;
        for (int s = 0; s < SL; s++) sc[s] *= inv;
    }
    __syncthreads();
    float4 acc = make_float4(0,0,0,0);
    int k = tid*4;
    for (int s = 0; s < SL; s++) {
        float ws = sc[s];
        float4 v = *(const float4*)(hsrc + ((long)s*BA + b)*HID + k);
        acc.x = fmaf(ws, v.x, acc.x); acc.y = fmaf(ws, v.y, acc.y);
        acc.z = fmaf(ws, v.z, acc.z); acc.w = fmaf(ws, v.w, acc.w);
    }
    *(float4*)(ctx + b*HID + k) = acc;
}

// ---------------- log-softmax ----------------
__global__ __launch_bounds__(256) void lsm_k(float* __restrict__ out)
{
    __shared__ float red[256];
    long m = blockIdx.x;
    float* row = out + m*VOUT;
    int tid = threadIdx.x;
    float mx = -1e30f;
    for (int i = tid; i < VOUT/4; i += 256) {
        float4 v = *(const float4*)(row + i*4);
        mx = fmaxf(mx, fmaxf(fmaxf(v.x, v.y), fmaxf(v.z, v.w)));
    }
    red[tid] = mx; __syncthreads();
    for (int o = 128; o > 0; o >>= 1) { if (tid < o) red[tid] = fmaxf(red[tid], red[tid+o]); __syncthreads(); }
    mx = red[0]; __syncthreads();
    float sum = 0.f;
    for (int i = tid; i < VOUT/4; i += 256) {
        float4 v = *(const float4*)(row + i*4);
        sum += expf(v.x-mx)+expf(v.y-mx)+expf(v.z-mx)+expf(v.w-mx);
    }
    red[tid] = sum; __syncthreads();
    for (int o = 128; o > 0; o >>= 1) { if (tid < o) red[tid] += red[tid+o]; __syncthreads(); }
    float lse = mx + logf(red[0]);
    for (int i = tid; i < VOUT/4; i += 256) {
        float4 v = *(const float4*)(row + i*4);
        v.x -= lse; v.y -= lse; v.z -= lse; v.w -= lse;
        *(float4*)(row + i*4) = v;
    }
}

static float* sym(const void* s){ void* p = nullptr; cudaGetSymbolAddress(&p, s); return (float*)p; }

extern "C" void kernel_launch(void* const* d_in, const int* in_sizes, int n_in,
                              void* d_out, int out_size)
{
    const int*   src   = (const int*)  d_in[0];
    const int*   tgt   = (const int*)  d_in[1];
    const float* embS  = (const float*)d_in[2];
    const float* embD  = (const float*)d_in[3];
    const float* eWih  = (const float*)d_in[4];
    const float* eWhh  = (const float*)d_in[5];
    const float* ebih  = (const float*)d_in[6];
    const float* ebhh  = (const float*)d_in[7];
    const float* d0Wih = (const float*)d_in[8];
    const float* d0Whh = (const float*)d_in[9];
    const float* d0bih = (const float*)d_in[10];
    const float* d0bhh = (const float*)d_in[11];
    const float* dWih  = (const float*)d_in[12];
    const float* dWhh  = (const float*)d_in[13];
    const float* dbih  = (const float*)d_in[14];
    const float* dbhh  = (const float*)d_in[15];
    const float* Wattn = (const float*)d_in[16];
    const float* Wcat  = (const float*)d_in[17];
    const float* bcat  = (const float*)d_in[18];
    const float* Wout  = (const float*)d_in[19];
    const float* bout  = (const float*)d_in[20];
    float* out = (float*)d_out;

    float* encx = sym(g_encx);  float* ency = sym(g_ency);
    float* encxg = sym(g_encxg);
    float* ehA = sym(g_enchA);  float* ehB = sym(g_enchB);
    float* ecc = sym(g_encc);
    float* h0 = sym(g_h0);      float* c0 = sym(g_c0);
    float* demb = sym(g_demb);  float* pre0 = sym(g_pre0);
    float* dhA = sym(g_dhA);    float* dhB = sym(g_dhB);
    float* dc  = sym(g_dc);
    float* htl = sym(g_htl);    float* ctx = sym(g_ctx);
    float* hAp = sym(g_hA);     float* hbt = sym(g_hbt);
    float* part = sym(g_part);
    __nv_bfloat16* wbf = (__nv_bfloat16*)sym(g_wbf);

    // ---- bf16 weight conversion (decoder recurrent path) ----
    {
        long n1 = 4194304L, n3 = 12582912L, nc = 1048576L;
        cvt_k<<<1024, 256>>>(wbf + OFF_W0H, d0Wih, 2048, 1024, 1024, n1);
        cvt_k<<<1024, 256>>>(wbf + OFF_W0R, d0Whh, 1024, 0, 1024, n1);
        cvt_k<<<1024, 256>>>(wbf + OFF_WIH, dWih, 1024, 0, 1024, n3);
        cvt_k<<<1024, 256>>>(wbf + OFF_WHH, dWhh, 1024, 0, 1024, n3);
        cvt_k<<<1024, 256>>>(wbf + OFF_WC1, Wcat, 2048, 0, 1024, nc);
        cvt_k<<<1024, 256>>>(wbf + OFF_WC2, Wcat, 2048, 1024, 1024, nc);
    }

    // ---- encoder ----
    embed_k<<<dim3(SL, BA), 256>>>(src, embS, encx, SL);
    float* xin = encx; float* yout = ency;
    for (int l = 0; l < NL; l++) {
        gemm_k<<<dim3(32, 7), 256>>>(xin, HID, eWih + (long)l*4096*1024, 1024, 1,
                                     ebih + l*4096, ebhh + l*4096, encxg, 4096,
                                     SL*BA, 4096, 1024, 0, 0);
        float* hi = ehA; float* ho = ehB;
        const float* Whh = eWhh + (long)l*4096*512;
        for (int st = 0; st < SL; st++) {
            enc_fused_k<<<64, 256>>>(Whh, encxg, hi, ho, ecc, yout,
                                     h0 + (long)l*BA*HID, c0 + (long)l*BA*HID, st);
            float* tmp = hi; hi = ho; ho = tmp;
        }
        float* t = xin; xin = yout; yout = t;
    }
    float* hsrc = xin;

    // ---- decoder precompute ----
    embed_k<<<dim3(TL, BA), 256>>>(tgt, embD, demb, TL);
    gemm_k<<<dim3(32, 7), 256>>>(demb, HID, d0Wih, 2048, 1, d0bih, d0bhh,
                                 pre0, 4096, TL*BA, 4096, 1024, 0, 0);
    gemm_k<<<dim3(8, 7), 256>>>(hsrc, HID, Wattn, 1024, 0, nullptr, nullptr,
                                hAp, HID, SL*BA, 1024, 1024, 0, 0);
    dinit_k<<<NL*BA*HID/256, 256>>>(dhA, h0, dc, c0, htl);

    // ---- decoder loop ----
    float* hi = dhA; float* ho = dhB;
    for (int t = 0; t < TL; t++) {
        mmbf_k<<<512, 256>>>(wbf + OFF_W0H, wbf + OFF_W0R, htl, hi, part, 4096);
        dec_cell_k<<<64, 256>>>(part, pre0 + (long)t*BA*4096, nullptr, nullptr,
                                dc, ho);
        for (int i = 0; i < NL-1; i++) {
            mmbf_k<<<512, 256>>>(wbf + OFF_WIH + (long)i*4194304,
                                 wbf + OFF_WHH + (long)i*4194304,
                                 ho + (long)i*BA*HID,
                                 hi + (long)(i+1)*BA*HID, part, 4096);
            dec_cell_k<<<64, 256>>>(part, nullptr, dbih + i*4096, dbhh + i*4096,
                                    dc + (long)(i+1)*BA*HID, ho + (long)(i+1)*BA*HID);
        }
        attn_k<<<BA, 256>>>(ho + (long)3*BA*HID, hAp, hsrc, ctx);
        mmbf_k<<<128, 256>>>(wbf + OFF_WC1, wbf + OFF_WC2,
                             ho + (long)3*BA*HID, ctx, part, 1024);
        htanh_k<<<64, 256>>>(part, bcat, htl, hbt, t);
        float* tmp = hi; hi = ho; ho = tmp;
    }

    // ---- generator (serial, after loop — keeps L2 clean during decode) ----
    gemm_k<<<dim3(250, 7), 256>>>(hbt, HID, Wout, 1024, 1, bout, nullptr,
                                  out, VOUT, TL*BA, VOUT, 1024, 1, 0);
    lsm_k<<<TL*BA, 256>>>(out);
}